// round 5
// baseline (speedup 1.0000x reference)
#include <cuda_runtime.h>
#include <cstdint>

// Problem constants
#define BB 8
#define CC 128
#define MM 16
#define HW 16384            // H*W = 128*128
#define PP 64               // spatial positions per tile
#define TT 4                // tiles per block
#define CHUNKS_PER_B 64     // HW / (PP*TT)
#define NBLK (BB * CHUNKS_PER_B)   // 512 main blocks

// Scratch: partial maxima per (block, m-1, c)
__device__ float g_partials[NBLK * 15 * CC];

__device__ __forceinline__ float neg_inf() { return __int_as_float(0xff800000); }

// Main kernel: block = (b, chunk of 256 spatial positions), 256 threads.
// Warps span channels (c) so mask bits are uniform per position per warp.
// neg[p][m] in {0, -inf} is precomputed once per position; each update is
// one FADD (fma pipe) + one FMNMX (alu pipe).
__global__ __launch_bounds__(256)
void vfm_main(const float* __restrict__ enc, const int* __restrict__ masks) {
    __shared__ float tile[CC][PP + 1];   // +1 pad: conflict-free column reads
    __shared__ float negs[PP][MM];       // 16B-aligned rows -> float4 loads
    __shared__ float comb[4][32][15];    // cross-half combine buffer

    const int bx    = blockIdx.x;
    const int b     = bx / CHUNKS_PER_B;
    const int chunk = bx % CHUNKS_PER_B;
    const int p0    = chunk * (PP * TT);

    const int tid  = threadIdx.x;
    const int w    = tid >> 5;
    const int lane = tid & 31;
    const int cg   = w & 3;        // channel group: c in [cg*32, cg*32+32)
    const int half = w >> 2;       // which 32-position half of the tile
    const int c    = cg * 32 + lane;

    float acc[15];
#pragma unroll
    for (int m = 0; m < 15; m++) acc[m] = neg_inf();

    const float* encb  = enc   + (size_t)b * CC * HW;
    const int*   maskb = masks + (size_t)b * MM * HW;

    for (int t = 0; t < TT; t++) {
        const int pb = p0 + t * PP;
        __syncthreads();   // previous tile fully consumed

        // ---- Phase 1a: stage enc[b, :, pb..pb+64) into SMEM (coalesced) ----
#pragma unroll
        for (int i = 0; i < (CC * PP) / 256; i++) {   // 32 iterations
            int idx = tid + i * 256;
            int cr  = idx >> 6;       // 0..127
            int pr  = idx & 63;       // 0..63
            tile[cr][pr] = encb[(size_t)cr * HW + pb + pr];
        }

        // ---- Phase 1b: expand mask bits to {0,-inf} per position ----
        if (tid < PP) {
            const int p = tid;
            const int* mp = maskb + pb + p;
            float nv[MM];
#pragma unroll
            for (int m = 0; m < MM; m++)
                nv[m] = mp[(size_t)m * HW] ? 0.0f : neg_inf();
#pragma unroll
            for (int q = 0; q < 4; q++)
                *reinterpret_cast<float4*>(&negs[p][q * 4]) =
                    make_float4(nv[4 * q], nv[4 * q + 1], nv[4 * q + 2], nv[4 * q + 3]);
        }
        __syncthreads();

        // ---- Phase 2: 15 accumulator updates per position (FADD+FMNMX) ----
        const int ps = half * 32;
#pragma unroll 4
        for (int p = ps; p < ps + 32; p++) {
            float v = tile[c][p];
            float4 n0 = *reinterpret_cast<const float4*>(&negs[p][0]);
            float4 n1 = *reinterpret_cast<const float4*>(&negs[p][4]);
            float4 n2 = *reinterpret_cast<const float4*>(&negs[p][8]);
            float4 n3 = *reinterpret_cast<const float4*>(&negs[p][12]);
            // m = 1..15 (skip mask channel 0)
            acc[0]  = fmaxf(acc[0],  v + n0.y);
            acc[1]  = fmaxf(acc[1],  v + n0.z);
            acc[2]  = fmaxf(acc[2],  v + n0.w);
            acc[3]  = fmaxf(acc[3],  v + n1.x);
            acc[4]  = fmaxf(acc[4],  v + n1.y);
            acc[5]  = fmaxf(acc[5],  v + n1.z);
            acc[6]  = fmaxf(acc[6],  v + n1.w);
            acc[7]  = fmaxf(acc[7],  v + n2.x);
            acc[8]  = fmaxf(acc[8],  v + n2.y);
            acc[9]  = fmaxf(acc[9],  v + n2.z);
            acc[10] = fmaxf(acc[10], v + n2.w);
            acc[11] = fmaxf(acc[11], v + n3.x);
            acc[12] = fmaxf(acc[12], v + n3.y);
            acc[13] = fmaxf(acc[13], v + n3.z);
            acc[14] = fmaxf(acc[14], v + n3.w);
        }
    }

    // ---- Combine the two position-halves, write partials ----
    __syncthreads();
    if (half == 1) {
#pragma unroll
        for (int m = 0; m < 15; m++) comb[cg][lane][m] = acc[m];
    }
    __syncthreads();
    if (half == 0) {
        float* outp = g_partials + (size_t)bx * 15 * CC + c;
#pragma unroll
        for (int m = 0; m < 15; m++) {
            float vmx = fmaxf(acc[m], comb[cg][lane][m]);
            outp[(size_t)m * CC] = vmx;   // coalesced per m
        }
    }
}

// Final reduce over the 64 chunks of each b. grid = (15, 8), 128 threads (c).
__global__ __launch_bounds__(128)
void vfm_reduce(float* __restrict__ out) {
    const int m = blockIdx.x;    // 0..14 (maps to mask channel m+1)
    const int b = blockIdx.y;    // 0..7
    const int c = threadIdx.x;   // 0..127
    float v = neg_inf();
    const float* pp = g_partials + ((size_t)(b * CHUNKS_PER_B) * 15 + m) * CC + c;
#pragma unroll 4
    for (int k = 0; k < CHUNKS_PER_B; k++)
        v = fmaxf(v, pp[(size_t)k * 15 * CC]);
    // out layout: [B, C, 15, 1] row-major
    out[((size_t)(b * CC + c)) * 15 + m] = v;
}

extern "C" void kernel_launch(void* const* d_in, const int* in_sizes, int n_in,
                              void* d_out, int out_size) {
    const float* enc   = (const float*)d_in[0];   // [8,128,128,128] f32
    const int*   masks = (const int*)d_in[1];     // [8,16,128,128] int32
    float* out = (float*)d_out;                   // [8,128,15,1] f32

    vfm_main<<<NBLK, 256>>>(enc, masks);
    vfm_reduce<<<dim3(15, 8), 128>>>(out);
}

// round 9
// speedup vs baseline: 1.7282x; 1.7282x over previous
#include <cuda_runtime.h>
#include <cuda_fp16.h>
#include <cstdint>

// Problem constants
#define BB 8
#define CC 128
#define MM 16
#define HW 16384            // H*W
#define PP 64               // spatial positions per tile
#define TT 4                // tiles per block
#define CHUNKS_PER_B 64     // HW / (PP*TT)
#define NBLK (BB * CHUNKS_PER_B)   // 512 main blocks

// Scratch: partial maxima per (block, m-1, c)
__device__ float g_partials[NBLK * 15 * CC];

__device__ __forceinline__ float neg_inff() { return __int_as_float(0xff800000); }

// Main kernel: block = (b, 256-position chunk), 256 threads.
// Warps span channels; mask bits are warp-uniform per position.
// Accumulators packed as 8 half2 (15 m's + 1 pad): per position
// 1 LDS.16 + 1 LDS.128 + 8 HADD2 + 8 HMAX2.
__global__ __launch_bounds__(256)
void vfm_main(const float* __restrict__ enc, const int* __restrict__ masks) {
    __shared__ __half tile_h[CC][PP + 2];            // stride 66 halves: conflict-free
    __shared__ __align__(16) __half2 negs2[PP][8];   // one 16B row per position
    __shared__ float comb[4][32][15];                // cross-half combine buffer

    const int bx    = blockIdx.x;
    const int b     = bx / CHUNKS_PER_B;
    const int chunk = bx % CHUNKS_PER_B;
    const int p0    = chunk * (PP * TT);

    const int tid  = threadIdx.x;
    const int w    = tid >> 5;
    const int lane = tid & 31;
    const int cg   = w & 3;        // channel group
    const int half = w >> 2;       // 32-position half of the tile
    const int c    = cg * 32 + lane;

    __half2 acc2[8];
    {
        unsigned ninf2 = 0xFC00FC00u;   // (-inf, -inf) in half2
        __half2 hn = *reinterpret_cast<__half2*>(&ninf2);
#pragma unroll
        for (int j = 0; j < 8; j++) acc2[j] = hn;
    }

    const float* encb  = enc   + (size_t)b * CC * HW;
    const int*   maskb = masks + (size_t)b * MM * HW;

    for (int t = 0; t < TT; t++) {
        const int pb = p0 + t * PP;
        __syncthreads();   // previous tile fully consumed

        // ---- Stage enc tile as half (coalesced float2 loads, half2 stores) ----
        // 128 rows x 32 half2-units; row stride in SMEM = 33 half2.
#pragma unroll
        for (int i = 0; i < (CC * PP / 2) / 256; i++) {   // 16 iterations
            int u  = tid + i * 256;
            int cr = u >> 5;          // 0..127
            int ph = u & 31;          // 0..31 (pairs of positions)
            float2 f2 = *reinterpret_cast<const float2*>(&encb[(size_t)cr * HW + pb + ph * 2]);
            __half2 h2 = __floats2half2_rn(f2.x, f2.y);
            *reinterpret_cast<__half2*>(&tile_h[cr][ph * 2]) = h2;
        }

        // ---- Expand mask bits to half2 {0,-inf} pairs; 256 threads active ----
        // acc2[j] covers mask channels (2j+1, 2j+2); thread (p, mg) builds j=2mg,2mg+1.
        {
            const int p  = tid & 63;
            const int mg = tid >> 6;          // 0..3
            const int* mp = maskb + pb + p;
            const int m0 = 4 * mg + 1;
            unsigned lo0 = mp[(size_t)(m0 + 0) * HW] ? 0u : 0xFC00u;
            unsigned hi0 = mp[(size_t)(m0 + 1) * HW] ? 0u : 0xFC00u;
            unsigned lo1 = mp[(size_t)(m0 + 2) * HW] ? 0u : 0xFC00u;
            unsigned hi1 = (m0 + 3 < MM) ? (mp[(size_t)(m0 + 3) * HW] ? 0u : 0xFC00u)
                                         : 0u;   // pad lane: harmless
            uint2 packed = make_uint2(lo0 | (hi0 << 16), lo1 | (hi1 << 16));
            *reinterpret_cast<uint2*>(&negs2[p][mg * 2]) = packed;
        }
        __syncthreads();

        // ---- Inner loop: 8 HADD2 + 8 HMAX2 per position ----
        const int ps = half * 32;
#pragma unroll 4
        for (int p = ps; p < ps + 32; p++) {
            __half2 v2 = __half2half2(tile_h[c][p]);
            uint4 nu = *reinterpret_cast<const uint4*>(&negs2[p][0]);   // LDS.128 broadcast
            __half2 n0 = *reinterpret_cast<__half2*>(&nu.x);
            __half2 n1 = *reinterpret_cast<__half2*>(&nu.y);
            __half2 n2 = *reinterpret_cast<__half2*>(&nu.z);
            __half2 n3 = *reinterpret_cast<__half2*>(&nu.w);
            acc2[0] = __hmax2(acc2[0], __hadd2(v2, n0));
            acc2[1] = __hmax2(acc2[1], __hadd2(v2, n1));
            acc2[2] = __hmax2(acc2[2], __hadd2(v2, n2));
            acc2[3] = __hmax2(acc2[3], __hadd2(v2, n3));
            uint4 nv = *reinterpret_cast<const uint4*>(&negs2[p][4]);
            __half2 n4 = *reinterpret_cast<__half2*>(&nv.x);
            __half2 n5 = *reinterpret_cast<__half2*>(&nv.y);
            __half2 n6 = *reinterpret_cast<__half2*>(&nv.z);
            __half2 n7 = *reinterpret_cast<__half2*>(&nv.w);
            acc2[4] = __hmax2(acc2[4], __hadd2(v2, n4));
            acc2[5] = __hmax2(acc2[5], __hadd2(v2, n5));
            acc2[6] = __hmax2(acc2[6], __hadd2(v2, n6));
            acc2[7] = __hmax2(acc2[7], __hadd2(v2, n7));
        }
    }

    // ---- Unpack to float, combine halves, write partials ----
    float acc[15];
#pragma unroll
    for (int j = 0; j < 8; j++) {
        acc[2 * j] = __low2float(acc2[j]);
        if (2 * j + 1 < 15) acc[2 * j + 1] = __high2float(acc2[j]);
    }

    __syncthreads();
    if (half == 1) {
#pragma unroll
        for (int m = 0; m < 15; m++) comb[cg][lane][m] = acc[m];
    }
    __syncthreads();
    if (half == 0) {
        float* outp = g_partials + (size_t)bx * 15 * CC + c;
#pragma unroll
        for (int m = 0; m < 15; m++) {
            float vmx = fmaxf(acc[m], comb[cg][lane][m]);
            outp[(size_t)m * CC] = vmx;   // coalesced per m
        }
    }
}

// Final reduce: grid (15, 8), 1024 threads. Each thread reduces 8 chunks
// (MLP=8, coalesced 128B per warp), SMEM tree for the last 8.
__global__ __launch_bounds__(1024)
void vfm_reduce(float* __restrict__ out) {
    __shared__ float red[8][128];
    const int m = blockIdx.x;            // 0..14
    const int b = blockIdx.y;            // 0..7
    const int c  = threadIdx.x & 127;    // channel
    const int kg = threadIdx.x >> 7;     // 0..7 chunk group
    float v = neg_inff();
    const float* pp = g_partials +
        ((size_t)(b * CHUNKS_PER_B + kg * 8) * 15 + m) * CC + c;
#pragma unroll
    for (int k = 0; k < 8; k++)
        v = fmaxf(v, pp[(size_t)k * 15 * CC]);
    red[kg][c] = v;
    __syncthreads();
    if (kg == 0) {
#pragma unroll
        for (int k = 1; k < 8; k++) v = fmaxf(v, red[k][c]);
        out[((size_t)(b * CC + c)) * 15 + m] = v;   // [B, C, 15, 1]
    }
}

extern "C" void kernel_launch(void* const* d_in, const int* in_sizes, int n_in,
                              void* d_out, int out_size) {
    const float* enc   = (const float*)d_in[0];   // [8,128,128,128] f32
    const int*   masks = (const int*)d_in[1];     // [8,16,128,128] int32
    float* out = (float*)d_out;                   // [8,128,15,1] f32

    vfm_main<<<NBLK, 256>>>(enc, masks);
    vfm_reduce<<<dim3(15, 8), 1024>>>(out);
}